// round 1
// baseline (speedup 1.0000x reference)
#include <cuda_runtime.h>
#include <math.h>

#define T_TOK 4096
#define H_DIM 1024
#define FF_DIM 2048
#define NEXP 8

// ---------------- device scratch (static globals: allocation-guard safe) ----
__device__ int   g_counts[NEXP];
__device__ int   g_tok[NEXP][T_TOK];
__device__ float g_wgt[NEXP][T_TOK];
// inner activations, capacity T rows per expert: 8*4096*2048 f32 = 256 MB
__device__ float g_inner[(size_t)NEXP * T_TOK * FF_DIM];

// ---------------- zero output accumulator + counts --------------------------
__global__ void zero_kernel(float* __restrict__ out) {
    size_t idx = (size_t)blockIdx.x * blockDim.x + threadIdx.x;
    const size_t n4 = (size_t)T_TOK * H_DIM / 4;
    if (idx < n4) ((float4*)out)[idx] = make_float4(0.f, 0.f, 0.f, 0.f);
    if (blockIdx.x == 0 && threadIdx.x < NEXP) g_counts[threadIdx.x] = 0;
}

// ---------------- router: 1 warp per token ----------------------------------
__global__ void router_kernel(const float* __restrict__ x,
                              const float* __restrict__ gw,
                              float* __restrict__ logits_out,
                              int write_logits) {
    int warp = (blockIdx.x * blockDim.x + threadIdx.x) >> 5;
    int lane = threadIdx.x & 31;
    if (warp >= T_TOK) return;

    const float* xr = x + (size_t)warp * H_DIM;
    float xv[32];
#pragma unroll
    for (int i = 0; i < 32; i++) xv[i] = xr[lane + 32 * i];

    float lg[NEXP];
#pragma unroll
    for (int e = 0; e < NEXP; e++) {
        const float* g = gw + (size_t)e * H_DIM;
        float s = 0.f;
#pragma unroll
        for (int i = 0; i < 32; i++) s += xv[i] * g[lane + 32 * i];
#pragma unroll
        for (int o = 16; o > 0; o >>= 1) s += __shfl_xor_sync(0xffffffffu, s, o);
        lg[e] = s;
    }

    if (lane == 0) {
        if (write_logits) {
#pragma unroll
            for (int e = 0; e < NEXP; e++)
                logits_out[(size_t)warp * NEXP + e] = lg[e];
        }
        // stable softmax (fp32, matches reference)
        float mx = lg[0];
#pragma unroll
        for (int e = 1; e < NEXP; e++) mx = fmaxf(mx, lg[e]);
        float p[NEXP], sum = 0.f;
#pragma unroll
        for (int e = 0; e < NEXP; e++) { p[e] = expf(lg[e] - mx); sum += p[e]; }
#pragma unroll
        for (int e = 0; e < NEXP; e++) p[e] /= sum;
        // top-2, first-index tie-break (matches lax.top_k)
        int i1 = 0;
#pragma unroll
        for (int e = 1; e < NEXP; e++) if (p[e] > p[i1]) i1 = e;
        int i2 = (i1 == 0) ? 1 : 0;
#pragma unroll
        for (int e = 0; e < NEXP; e++) if (e != i1 && p[e] > p[i2]) i2 = e;
        float s2 = p[i1] + p[i2];
        float wa = p[i1] / s2, wb = p[i2] / s2;
        int pos = atomicAdd(&g_counts[i1], 1);
        g_tok[i1][pos] = warp; g_wgt[i1][pos] = wa;
        pos = atomicAdd(&g_counts[i2], 1);
        g_tok[i2][pos] = warp; g_wgt[i2][pos] = wb;
    }
}

// ---------------- GEMM1: inner = silu(Xg @ W1^T) * (Xg @ W3^T) --------------
// tile 128(M) x 64(N) x 16(K), 256 threads, 8x4 microtile, two B matrices
#define G1_BM 128
#define G1_BN 64
#define G1_BK 16

__global__ void __launch_bounds__(256, 2)
gemm1_kernel(const float* __restrict__ x,
             const float* __restrict__ w1,
             const float* __restrict__ w3) {
    const int e = blockIdx.z;
    const int n = g_counts[e];
    const int row0 = blockIdx.y * G1_BM;
    if (row0 >= n) return;
    const int ff0 = blockIdx.x * G1_BN;

    __shared__ float As[G1_BK][G1_BM + 4];   // transposed, +4 pad
    __shared__ float B1s[G1_BK][G1_BN + 4];
    __shared__ float B3s[G1_BK][G1_BN + 4];

    const int tid = threadIdx.x;
    const int tx = tid & 15, ty = tid >> 4;

    // per-thread gathered tokens for the A staging (2 float4 loads / tile)
    int tokA[2];
#pragma unroll
    for (int it = 0; it < 2; it++) {
        int m = (tid + it * 256) >> 2;
        int r = row0 + m;
        tokA[it] = (r < n) ? g_tok[e][r] : -1;
    }
    const int nB = tid >> 2;     // 0..63
    const int kq = tid & 3;      // 0..3
    const float* p1 = w1 + ((size_t)e * FF_DIM + ff0 + nB) * H_DIM + (kq << 2);
    const float* p3 = w3 + ((size_t)e * FF_DIM + ff0 + nB) * H_DIM + (kq << 2);

    float acc1[8][4], acc3[8][4];
#pragma unroll
    for (int i = 0; i < 8; i++)
#pragma unroll
        for (int j = 0; j < 4; j++) { acc1[i][j] = 0.f; acc3[i][j] = 0.f; }

    for (int k0 = 0; k0 < H_DIM; k0 += G1_BK) {
        // stage A (gathered, transposed)
#pragma unroll
        for (int it = 0; it < 2; it++) {
            int id = tid + it * 256;
            int m = id >> 2, kqa = id & 3;
            float4 v = make_float4(0.f, 0.f, 0.f, 0.f);
            if (tokA[it] >= 0)
                v = *(const float4*)(x + (size_t)tokA[it] * H_DIM + k0 + (kqa << 2));
            As[(kqa << 2) + 0][m] = v.x;
            As[(kqa << 2) + 1][m] = v.y;
            As[(kqa << 2) + 2][m] = v.z;
            As[(kqa << 2) + 3][m] = v.w;
        }
        // stage B1/B3 (transposed)
        {
            float4 v = *(const float4*)(p1 + k0);
            B1s[(kq << 2) + 0][nB] = v.x; B1s[(kq << 2) + 1][nB] = v.y;
            B1s[(kq << 2) + 2][nB] = v.z; B1s[(kq << 2) + 3][nB] = v.w;
            v = *(const float4*)(p3 + k0);
            B3s[(kq << 2) + 0][nB] = v.x; B3s[(kq << 2) + 1][nB] = v.y;
            B3s[(kq << 2) + 2][nB] = v.z; B3s[(kq << 2) + 3][nB] = v.w;
        }
        __syncthreads();

#pragma unroll
        for (int k = 0; k < G1_BK; k++) {
            float4 a0 = *(const float4*)&As[k][ty * 8];
            float4 a1 = *(const float4*)&As[k][ty * 8 + 4];
            float4 b1 = *(const float4*)&B1s[k][tx * 4];
            float4 b3 = *(const float4*)&B3s[k][tx * 4];
            float a[8] = {a0.x, a0.y, a0.z, a0.w, a1.x, a1.y, a1.z, a1.w};
            float bb1[4] = {b1.x, b1.y, b1.z, b1.w};
            float bb3[4] = {b3.x, b3.y, b3.z, b3.w};
#pragma unroll
            for (int i = 0; i < 8; i++)
#pragma unroll
                for (int j = 0; j < 4; j++) {
                    acc1[i][j] += a[i] * bb1[j];
                    acc3[i][j] += a[i] * bb3[j];
                }
        }
        __syncthreads();
    }

    // fused SwiGLU epilogue -> g_inner
#pragma unroll
    for (int i = 0; i < 8; i++) {
        int r = row0 + ty * 8 + i;
        if (r < n) {
            float4 v;
            float* dst = &g_inner[((size_t)e * T_TOK + r) * FF_DIM + ff0 + tx * 4];
            float s0 = acc1[i][0] / (1.f + expf(-acc1[i][0]));
            float s1 = acc1[i][1] / (1.f + expf(-acc1[i][1]));
            float s2 = acc1[i][2] / (1.f + expf(-acc1[i][2]));
            float s3 = acc1[i][3] / (1.f + expf(-acc1[i][3]));
            v.x = s0 * acc3[i][0]; v.y = s1 * acc3[i][1];
            v.z = s2 * acc3[i][2]; v.w = s3 * acc3[i][3];
            *(float4*)dst = v;
        }
    }
}

// ---------------- GEMM2: out += w * (inner @ W2^T), scatter-add -------------
// tile 128(M) x 128(N) x 16(K), 256 threads, 8x8 microtile
#define G2_BM 128
#define G2_BN 128
#define G2_BK 16

__global__ void __launch_bounds__(256, 1)
gemm2_kernel(const float* __restrict__ w2, float* __restrict__ out) {
    const int e = blockIdx.z;
    const int n = g_counts[e];
    const int row0 = blockIdx.y * G2_BM;
    if (row0 >= n) return;
    const int h0 = blockIdx.x * G2_BN;

    __shared__ float As[G2_BK][G2_BM + 4];
    __shared__ float Bs[G2_BK][G2_BN + 4];

    const int tid = threadIdx.x;
    const int tx = tid & 15, ty = tid >> 4;

    float acc[8][8];
#pragma unroll
    for (int i = 0; i < 8; i++)
#pragma unroll
        for (int j = 0; j < 8; j++) acc[i][j] = 0.f;

    const float* Abase = g_inner + ((size_t)e * T_TOK + row0) * FF_DIM;
    const float* Bbase = w2 + ((size_t)e * H_DIM + h0) * FF_DIM;

    for (int k0 = 0; k0 < FF_DIM; k0 += G2_BK) {
#pragma unroll
        for (int it = 0; it < 2; it++) {
            int id = tid + it * 256;
            int m = id >> 2, kqa = id & 3;
            float4 v = *(const float4*)(Abase + (size_t)m * FF_DIM + k0 + (kqa << 2));
            As[(kqa << 2) + 0][m] = v.x; As[(kqa << 2) + 1][m] = v.y;
            As[(kqa << 2) + 2][m] = v.z; As[(kqa << 2) + 3][m] = v.w;
        }
#pragma unroll
        for (int it = 0; it < 2; it++) {
            int id = tid + it * 256;
            int nn = id >> 2, kqa = id & 3;
            float4 v = *(const float4*)(Bbase + (size_t)nn * FF_DIM + k0 + (kqa << 2));
            Bs[(kqa << 2) + 0][nn] = v.x; Bs[(kqa << 2) + 1][nn] = v.y;
            Bs[(kqa << 2) + 2][nn] = v.z; Bs[(kqa << 2) + 3][nn] = v.w;
        }
        __syncthreads();

#pragma unroll
        for (int k = 0; k < G2_BK; k++) {
            float4 a0 = *(const float4*)&As[k][ty * 8];
            float4 a1 = *(const float4*)&As[k][ty * 8 + 4];
            float4 b0 = *(const float4*)&Bs[k][tx * 8];
            float4 b1 = *(const float4*)&Bs[k][tx * 8 + 4];
            float a[8] = {a0.x, a0.y, a0.z, a0.w, a1.x, a1.y, a1.z, a1.w};
            float b[8] = {b0.x, b0.y, b0.z, b0.w, b1.x, b1.y, b1.z, b1.w};
#pragma unroll
            for (int i = 0; i < 8; i++)
#pragma unroll
                for (int j = 0; j < 8; j++) acc[i][j] += a[i] * b[j];
        }
        __syncthreads();
    }

#pragma unroll
    for (int i = 0; i < 8; i++) {
        int r = row0 + ty * 8 + i;
        if (r < n) {
            int tok = g_tok[e][r];
            float wt = g_wgt[e][r];
            float* orow = out + (size_t)tok * H_DIM + h0 + tx * 8;
#pragma unroll
            for (int j = 0; j < 8; j++) atomicAdd(&orow[j], wt * acc[i][j]);
        }
    }
}

// ---------------- launch -----------------------------------------------------
extern "C" void kernel_launch(void* const* d_in, const int* in_sizes, int n_in,
                              void* d_out, int out_size) {
    const float* x  = (const float*)d_in[0];  // hidden_states [2,2048,1024]
    const float* gw = (const float*)d_in[1];  // gate_w [8,1024]
    const float* w1 = (const float*)d_in[2];  // [8,2048,1024]
    const float* w2 = (const float*)d_in[3];  // [8,1024,2048]
    const float* w3 = (const float*)d_in[4];  // [8,2048,1024]
    float* out = (float*)d_out;

    const size_t final_elems = (size_t)T_TOK * H_DIM;
    int write_logits = ((size_t)out_size >= final_elems + (size_t)T_TOK * NEXP) ? 1 : 0;
    float* logits = out + final_elems;

    zero_kernel<<<(T_TOK * H_DIM / 4 + 255) / 256, 256>>>(out);
    router_kernel<<<T_TOK / 4, 128>>>(x, gw, logits, write_logits);

    dim3 g1(FF_DIM / G1_BN, T_TOK / G1_BM, NEXP);
    gemm1_kernel<<<g1, 256>>>(x, w1, w3);

    dim3 g2(H_DIM / G2_BN, T_TOK / G2_BM, NEXP);
    gemm2_kernel<<<g2, 256>>>(w2, out);
}

// round 3
// speedup vs baseline: 2.7916x; 2.7916x over previous
#include <cuda_runtime.h>
#include <math.h>
#include <stdint.h>

#define T_TOK 4096
#define H_DIM 1024
#define FF_DIM 2048
#define NEXP 8

// ---------------- device scratch (allocation-guard safe) --------------------
__device__ int   g_counts[NEXP];
__device__ int   g_tok[NEXP][T_TOK];            // packed: tok | slot<<16
__device__ float g_wslot[2 * T_TOK];            // combine weights per slot
__device__ float g_inner[(size_t)NEXP * T_TOK * FF_DIM];   // 256 MB
__device__ float g_comb[(size_t)2 * T_TOK * H_DIM];        // 32 MB

// ---------------- helpers ----------------------------------------------------
__device__ __forceinline__ uint32_t tf32u(float x) {
    uint32_t u; asm("cvt.rna.tf32.f32 %0, %1;" : "=r"(u) : "f"(x)); return u;
}
__device__ __forceinline__ void mma8(float* c, const uint32_t* a, const uint32_t* b) {
    asm volatile(
        "mma.sync.aligned.m16n8k8.row.col.f32.tf32.tf32.f32 "
        "{%0,%1,%2,%3}, {%4,%5,%6,%7}, {%8,%9}, {%0,%1,%2,%3};"
        : "+f"(c[0]), "+f"(c[1]), "+f"(c[2]), "+f"(c[3])
        : "r"(a[0]), "r"(a[1]), "r"(a[2]), "r"(a[3]), "r"(b[0]), "r"(b[1]));
}
__device__ __forceinline__ uint4 cvt4(float4 v) {
    uint4 u; u.x = tf32u(v.x); u.y = tf32u(v.y); u.z = tf32u(v.z); u.w = tf32u(v.w);
    return u;
}

// ---------------- zero counts ------------------------------------------------
__global__ void zero_counts_kernel() {
    if (threadIdx.x < NEXP) g_counts[threadIdx.x] = 0;
}

// ---------------- router: 1 warp per token ----------------------------------
__global__ void router_kernel(const float* __restrict__ x,
                              const float* __restrict__ gw,
                              float* __restrict__ logits_out,
                              int write_logits) {
    int warp = (blockIdx.x * blockDim.x + threadIdx.x) >> 5;
    int lane = threadIdx.x & 31;
    if (warp >= T_TOK) return;

    const float* xr = x + (size_t)warp * H_DIM;
    float xv[32];
#pragma unroll
    for (int i = 0; i < 32; i++) xv[i] = xr[lane + 32 * i];

    float lg[NEXP];
#pragma unroll
    for (int e = 0; e < NEXP; e++) {
        const float* g = gw + (size_t)e * H_DIM;
        float s = 0.f;
#pragma unroll
        for (int i = 0; i < 32; i++) s += xv[i] * g[lane + 32 * i];
#pragma unroll
        for (int o = 16; o > 0; o >>= 1) s += __shfl_xor_sync(0xffffffffu, s, o);
        lg[e] = s;
    }

    if (lane == 0) {
        if (write_logits) {
#pragma unroll
            for (int e = 0; e < NEXP; e++)
                logits_out[(size_t)warp * NEXP + e] = lg[e];
        }
        float mx = lg[0];
#pragma unroll
        for (int e = 1; e < NEXP; e++) mx = fmaxf(mx, lg[e]);
        float p[NEXP], sum = 0.f;
#pragma unroll
        for (int e = 0; e < NEXP; e++) { p[e] = expf(lg[e] - mx); sum += p[e]; }
#pragma unroll
        for (int e = 0; e < NEXP; e++) p[e] /= sum;
        int i1 = 0;
#pragma unroll
        for (int e = 1; e < NEXP; e++) if (p[e] > p[i1]) i1 = e;
        int i2 = (i1 == 0) ? 1 : 0;
#pragma unroll
        for (int e = 0; e < NEXP; e++) if (e != i1 && p[e] > p[i2]) i2 = e;
        float s2 = p[i1] + p[i2];
        int pos = atomicAdd(&g_counts[i1], 1);
        g_tok[i1][pos] = warp;                 // slot 0
        pos = atomicAdd(&g_counts[i2], 1);
        g_tok[i2][pos] = warp | 0x10000;       // slot 1
        g_wslot[warp]         = p[i1] / s2;
        g_wslot[T_TOK + warp] = p[i2] / s2;
    }
}

// ---------------- GEMM1: inner = silu(Xg@W1^T)*(Xg@W3^T) (mma tf32) ---------
// block tile 128(M) x 64(N, per matrix) x 32(K); 8 warps = 4M x 2N,
// warp tile 32x32 for each of w1/w3. smem stride 36 floats (conflict-free).
#define SS 36

__global__ void __launch_bounds__(256, 2)
gemm1_tc(const float* __restrict__ x,
         const float* __restrict__ w1,
         const float* __restrict__ w3) {
    __shared__ uint32_t As[128 * SS];
    __shared__ uint32_t B1s[64 * SS];
    __shared__ uint32_t B3s[64 * SS];

    const int e = blockIdx.z;
    const int n = g_counts[e];
    const int row0 = blockIdx.y * 128;
    if (row0 >= n) return;
    const int ff0 = blockIdx.x * 64;

    const int tid = threadIdx.x;
    const int wid = tid >> 5, lane = tid & 31;
    const int wm = wid & 3, wn = wid >> 2;
    const int g = lane >> 2, t = lane & 3;

    // staging maps
    const float* apt[4]; int aoff[4];
#pragma unroll
    for (int i = 0; i < 4; i++) {
        int idx = tid + 256 * i;
        int arow = idx >> 3, aq = idx & 7;
        aoff[i] = arow * SS + aq * 4;
        int r = row0 + arow;
        if (r < n) {
            int tok = g_tok[e][r] & 0xFFFF;
            apt[i] = x + (size_t)tok * H_DIM + aq * 4;
        } else apt[i] = 0;
    }
    const float* b1pt[2]; const float* b3pt[2]; int boff[2];
#pragma unroll
    for (int i = 0; i < 2; i++) {
        int idx = tid + 256 * i;
        int brow = idx >> 3, bq = idx & 7;
        boff[i] = brow * SS + bq * 4;
        b1pt[i] = w1 + ((size_t)e * FF_DIM + ff0 + brow) * H_DIM + bq * 4;
        b3pt[i] = w3 + ((size_t)e * FF_DIM + ff0 + brow) * H_DIM + bq * 4;
    }

    float4 ra[4], rb1[2], rb3[2];
#define G1_LOAD(k0) do { \
    _Pragma("unroll") for (int i = 0; i < 4; i++) \
        ra[i] = apt[i] ? *(const float4*)(apt[i] + (k0)) : make_float4(0.f,0.f,0.f,0.f); \
    _Pragma("unroll") for (int i = 0; i < 2; i++) { \
        rb1[i] = *(const float4*)(b1pt[i] + (k0)); \
        rb3[i] = *(const float4*)(b3pt[i] + (k0)); } } while (0)
#define G1_STORE() do { \
    _Pragma("unroll") for (int i = 0; i < 4; i++) *(uint4*)&As[aoff[i]] = cvt4(ra[i]); \
    _Pragma("unroll") for (int i = 0; i < 2; i++) { \
        *(uint4*)&B1s[boff[i]] = cvt4(rb1[i]); \
        *(uint4*)&B3s[boff[i]] = cvt4(rb3[i]); } } while (0)

    float acc1[2][4][4], acc3[2][4][4];
#pragma unroll
    for (int mb = 0; mb < 2; mb++)
#pragma unroll
        for (int nb = 0; nb < 4; nb++)
#pragma unroll
            for (int j = 0; j < 4; j++) { acc1[mb][nb][j] = 0.f; acc3[mb][nb][j] = 0.f; }

    const uint32_t* Ab  = &As[(wm * 32 + g) * SS + t];
    const uint32_t* B1b = &B1s[(wn * 32 + g) * SS + t];
    const uint32_t* B3b = &B3s[(wn * 32 + g) * SS + t];

    G1_LOAD(0);
    G1_STORE();
    __syncthreads();

    const int NIT = H_DIM / 32;
    for (int it = 0; it < NIT; ++it) {
        const bool more = (it + 1 < NIT);
        if (more) G1_LOAD((it + 1) * 32);
#pragma unroll
        for (int kk = 0; kk < 4; kk++) {
            uint32_t a[2][4], b1[4][2], b3[4][2];
#pragma unroll
            for (int mb = 0; mb < 2; mb++) {
                int base = mb * 16 * SS + kk * 8;
                a[mb][0] = Ab[base];
                a[mb][1] = Ab[base + 8 * SS];
                a[mb][2] = Ab[base + 4];
                a[mb][3] = Ab[base + 8 * SS + 4];
            }
#pragma unroll
            for (int nb = 0; nb < 4; nb++) {
                int bb = nb * 8 * SS + kk * 8;
                b1[nb][0] = B1b[bb]; b1[nb][1] = B1b[bb + 4];
                b3[nb][0] = B3b[bb]; b3[nb][1] = B3b[bb + 4];
            }
#pragma unroll
            for (int mb = 0; mb < 2; mb++)
#pragma unroll
                for (int nb = 0; nb < 4; nb++) {
                    mma8(acc1[mb][nb], a[mb], b1[nb]);
                    mma8(acc3[mb][nb], a[mb], b3[nb]);
                }
        }
        __syncthreads();
        if (more) { G1_STORE(); __syncthreads(); }
    }

    // fused SwiGLU epilogue -> g_inner
#pragma unroll
    for (int mb = 0; mb < 2; mb++) {
        int r0 = row0 + wm * 32 + mb * 16 + g;
        int r1 = r0 + 8;
#pragma unroll
        for (int nb = 0; nb < 4; nb++) {
            int col = ff0 + wn * 32 + nb * 8 + 2 * t;
            if (r0 < n) {
                float a0 = acc1[mb][nb][0], a1 = acc1[mb][nb][1];
                float2 v;
                v.x = (a0 / (1.f + expf(-a0))) * acc3[mb][nb][0];
                v.y = (a1 / (1.f + expf(-a1))) * acc3[mb][nb][1];
                *(float2*)&g_inner[((size_t)e * T_TOK + r0) * FF_DIM + col] = v;
            }
            if (r1 < n) {
                float a2 = acc1[mb][nb][2], a3 = acc1[mb][nb][3];
                float2 v;
                v.x = (a2 / (1.f + expf(-a2))) * acc3[mb][nb][2];
                v.y = (a3 / (1.f + expf(-a3))) * acc3[mb][nb][3];
                *(float2*)&g_inner[((size_t)e * T_TOK + r1) * FF_DIM + col] = v;
            }
        }
    }
}

// ---------------- GEMM2: comb[slot][tok] = inner @ W2^T (mma tf32) ----------
// block tile 128 x 128 x 32; 8 warps = 4M x 2N, warp tile 32x64.
__global__ void __launch_bounds__(256, 2)
gemm2_tc(const float* __restrict__ w2) {
    __shared__ uint32_t As[128 * SS];
    __shared__ uint32_t Bs[128 * SS];

    const int e = blockIdx.z;
    const int n = g_counts[e];
    const int row0 = blockIdx.y * 128;
    if (row0 >= n) return;
    const int h0 = blockIdx.x * 128;

    const int tid = threadIdx.x;
    const int wid = tid >> 5, lane = tid & 31;
    const int wm = wid & 3, wn = wid >> 2;
    const int g = lane >> 2, t = lane & 3;

    const float* apt[4]; int aoff[4];
    const float* bpt[4]; int boff[4];
#pragma unroll
    for (int i = 0; i < 4; i++) {
        int idx = tid + 256 * i;
        int row = idx >> 3, q = idx & 7;
        aoff[i] = row * SS + q * 4;
        boff[i] = aoff[i];
        apt[i] = g_inner + ((size_t)e * T_TOK + row0 + row) * FF_DIM + q * 4;
        bpt[i] = w2 + ((size_t)e * H_DIM + h0 + row) * FF_DIM + q * 4;
    }

    float4 ra[4], rb[4];
#define G2_LOAD(k0) do { \
    _Pragma("unroll") for (int i = 0; i < 4; i++) { \
        ra[i] = *(const float4*)(apt[i] + (k0)); \
        rb[i] = *(const float4*)(bpt[i] + (k0)); } } while (0)
#define G2_STORE() do { \
    _Pragma("unroll") for (int i = 0; i < 4; i++) { \
        *(uint4*)&As[aoff[i]] = cvt4(ra[i]); \
        *(uint4*)&Bs[boff[i]] = cvt4(rb[i]); } } while (0)

    float acc[2][8][4];
#pragma unroll
    for (int mb = 0; mb < 2; mb++)
#pragma unroll
        for (int nb = 0; nb < 8; nb++)
#pragma unroll
            for (int j = 0; j < 4; j++) acc[mb][nb][j] = 0.f;

    const uint32_t* Ab = &As[(wm * 32 + g) * SS + t];
    const uint32_t* Bb = &Bs[(wn * 64 + g) * SS + t];

    G2_LOAD(0);
    G2_STORE();
    __syncthreads();

    const int NIT = FF_DIM / 32;
    for (int it = 0; it < NIT; ++it) {
        const bool more = (it + 1 < NIT);
        if (more) G2_LOAD((it + 1) * 32);
#pragma unroll
        for (int kk = 0; kk < 4; kk++) {
            uint32_t a[2][4], b[8][2];
#pragma unroll
            for (int mb = 0; mb < 2; mb++) {
                int base = mb * 16 * SS + kk * 8;
                a[mb][0] = Ab[base];
                a[mb][1] = Ab[base + 8 * SS];
                a[mb][2] = Ab[base + 4];
                a[mb][3] = Ab[base + 8 * SS + 4];
            }
#pragma unroll
            for (int nb = 0; nb < 8; nb++) {
                int bb = nb * 8 * SS + kk * 8;
                b[nb][0] = Bb[bb]; b[nb][1] = Bb[bb + 4];
            }
#pragma unroll
            for (int mb = 0; mb < 2; mb++)
#pragma unroll
                for (int nb = 0; nb < 8; nb++)
                    mma8(acc[mb][nb], a[mb], b[nb]);
        }
        __syncthreads();
        if (more) { G2_STORE(); __syncthreads(); }
    }

    // non-atomic scatter into per-slot combine buffers
#pragma unroll
    for (int mb = 0; mb < 2; mb++) {
        int r0 = row0 + wm * 32 + mb * 16 + g;
        int r1 = r0 + 8;
        int pk0 = (r0 < n) ? g_tok[e][r0] : -1;
        int pk1 = (r1 < n) ? g_tok[e][r1] : -1;
        float* d0 = (pk0 >= 0)
            ? &g_comb[((size_t)(pk0 >> 16) * T_TOK + (pk0 & 0xFFFF)) * H_DIM] : 0;
        float* d1 = (pk1 >= 0)
            ? &g_comb[((size_t)(pk1 >> 16) * T_TOK + (pk1 & 0xFFFF)) * H_DIM] : 0;
#pragma unroll
        for (int nb = 0; nb < 8; nb++) {
            int col = h0 + wn * 64 + nb * 8 + 2 * t;
            if (d0) { float2 v; v.x = acc[mb][nb][0]; v.y = acc[mb][nb][1];
                      *(float2*)&d0[col] = v; }
            if (d1) { float2 v; v.x = acc[mb][nb][2]; v.y = acc[mb][nb][3];
                      *(float2*)&d1[col] = v; }
        }
    }
}

// ---------------- combine: out = w0*comb0 + w1*comb1 ------------------------
__global__ void combine_kernel(float* __restrict__ out) {
    int idx = blockIdx.x * blockDim.x + threadIdx.x;
    const int nq = T_TOK * H_DIM / 4;
    if (idx >= nq) return;
    int tk = idx / (H_DIM / 4);
    float w0 = g_wslot[tk], w1 = g_wslot[T_TOK + tk];
    float4 v0 = ((const float4*)g_comb)[idx];
    float4 v1 = ((const float4*)g_comb)[(size_t)(T_TOK * H_DIM / 4) + idx];
    float4 r;
    r.x = w0 * v0.x + w1 * v1.x;
    r.y = w0 * v0.y + w1 * v1.y;
    r.z = w0 * v0.z + w1 * v1.z;
    r.w = w0 * v0.w + w1 * v1.w;
    ((float4*)out)[idx] = r;
}

// ---------------- launch -----------------------------------------------------
extern "C" void kernel_launch(void* const* d_in, const int* in_sizes, int n_in,
                              void* d_out, int out_size) {
    const float* x  = (const float*)d_in[0];  // [2,2048,1024]
    const float* gw = (const float*)d_in[1];  // [8,1024]
    const float* w1 = (const float*)d_in[2];  // [8,2048,1024]
    const float* w2 = (const float*)d_in[3];  // [8,1024,2048]
    const float* w3 = (const float*)d_in[4];  // [8,2048,1024]
    float* out = (float*)d_out;

    const size_t final_elems = (size_t)T_TOK * H_DIM;
    int write_logits = ((size_t)out_size >= final_elems + (size_t)T_TOK * NEXP) ? 1 : 0;
    float* logits = out + final_elems;

    zero_counts_kernel<<<1, 32>>>();
    router_kernel<<<T_TOK / 4, 128>>>(x, gw, logits, write_logits);

    dim3 g1(FF_DIM / 64, T_TOK / 128, NEXP);   // (32, 32, 8)
    gemm1_tc<<<g1, 256>>>(x, w1, w3);

    dim3 g2(H_DIM / 128, T_TOK / 128, NEXP);   // (8, 32, 8)
    gemm2_tc<<<g2, 256>>>(w2);

    combine_kernel<<<(T_TOK * H_DIM / 4 + 255) / 256, 256>>>(out);
}

// round 5
// speedup vs baseline: 3.0269x; 1.0843x over previous
#include <cuda_runtime.h>
#include <math.h>
#include <stdint.h>

#define T_TOK 4096
#define H_DIM 1024
#define FF_DIM 2048
#define NEXP 8
#define SS 36
#define STAGES 3

// ---------------- device scratch (allocation-guard safe) --------------------
__device__ int   g_counts[NEXP];
__device__ int   g_tok[NEXP][T_TOK];            // packed: tok | slot<<16
__device__ float g_wslot[2 * T_TOK];
__device__ float g_inner[(size_t)NEXP * T_TOK * FF_DIM];   // 256 MB
__device__ float g_comb[(size_t)2 * T_TOK * H_DIM];        // 32 MB
__device__ float g_w1r[(size_t)NEXP * FF_DIM * H_DIM];     // 64 MB (tf32-rounded)
__device__ float g_w3r[(size_t)NEXP * FF_DIM * H_DIM];     // 64 MB
__device__ float g_w2r[(size_t)NEXP * H_DIM * FF_DIM];     // 64 MB
__device__ float g_xr[(size_t)T_TOK * H_DIM];              // 16 MB

// ---------------- helpers ----------------------------------------------------
__device__ __forceinline__ uint32_t tf32u(float x) {
    uint32_t u; asm("cvt.rna.tf32.f32 %0, %1;" : "=r"(u) : "f"(x)); return u;
}
__device__ __forceinline__ uint4 cvt4(float4 v) {
    uint4 u; u.x = tf32u(v.x); u.y = tf32u(v.y); u.z = tf32u(v.z); u.w = tf32u(v.w);
    return u;
}
__device__ __forceinline__ void mma8(float* c, const uint32_t* a, const uint32_t* b) {
    asm volatile(
        "mma.sync.aligned.m16n8k8.row.col.f32.tf32.tf32.f32 "
        "{%0,%1,%2,%3}, {%4,%5,%6,%7}, {%8,%9}, {%0,%1,%2,%3};"
        : "+f"(c[0]), "+f"(c[1]), "+f"(c[2]), "+f"(c[3])
        : "r"(a[0]), "r"(a[1]), "r"(a[2]), "r"(a[3]), "r"(b[0]), "r"(b[1]));
}
#define CP16(dst, src) \
    asm volatile("cp.async.cg.shared.global [%0], [%1], 16;" \
                 :: "r"(dst), "l"(src) : "memory")
#define CPCOMMIT() asm volatile("cp.async.commit_group;" ::: "memory")
#define CPWAIT1()  asm volatile("cp.async.wait_group 1;" ::: "memory")
#define CPWAIT0()  asm volatile("cp.async.wait_group 0;" ::: "memory")

// ---------------- prolog: round weights to tf32, zero counts ----------------
__global__ void round_weights_kernel(const float* __restrict__ w1,
                                     const float* __restrict__ w2,
                                     const float* __restrict__ w3) {
    size_t i = (size_t)blockIdx.x * blockDim.x + threadIdx.x;
    const size_t n4 = (size_t)NEXP * FF_DIM * H_DIM / 4;
    if (i < n4) {
        ((uint4*)g_w1r)[i] = cvt4(((const float4*)w1)[i]);
        ((uint4*)g_w3r)[i] = cvt4(((const float4*)w3)[i]);
        ((uint4*)g_w2r)[i] = cvt4(((const float4*)w2)[i]);
    }
    if (blockIdx.x == 0 && threadIdx.x < NEXP) g_counts[threadIdx.x] = 0;
}

// ---------------- router: 1 warp per token; also writes rounded x -----------
__global__ void router_kernel(const float* __restrict__ x,
                              const float* __restrict__ gw,
                              float* __restrict__ logits_out,
                              int write_logits) {
    int warp = (blockIdx.x * blockDim.x + threadIdx.x) >> 5;
    int lane = threadIdx.x & 31;
    if (warp >= T_TOK) return;

    const float* xr = x + (size_t)warp * H_DIM;
    float xv[32];
#pragma unroll
    for (int i = 0; i < 32; i++) xv[i] = xr[lane + 32 * i];
#pragma unroll
    for (int i = 0; i < 32; i++)
        ((uint32_t*)g_xr)[(size_t)warp * H_DIM + lane + 32 * i] = tf32u(xv[i]);

    float lg[NEXP];
#pragma unroll
    for (int e = 0; e < NEXP; e++) {
        const float* g = gw + (size_t)e * H_DIM;
        float s = 0.f;
#pragma unroll
        for (int i = 0; i < 32; i++) s += xv[i] * g[lane + 32 * i];
#pragma unroll
        for (int o = 16; o > 0; o >>= 1) s += __shfl_xor_sync(0xffffffffu, s, o);
        lg[e] = s;
    }

    if (lane == 0) {
        if (write_logits) {
#pragma unroll
            for (int e = 0; e < NEXP; e++)
                logits_out[(size_t)warp * NEXP + e] = lg[e];
        }
        float mx = lg[0];
#pragma unroll
        for (int e = 1; e < NEXP; e++) mx = fmaxf(mx, lg[e]);
        float p[NEXP], sum = 0.f;
#pragma unroll
        for (int e = 0; e < NEXP; e++) { p[e] = expf(lg[e] - mx); sum += p[e]; }
#pragma unroll
        for (int e = 0; e < NEXP; e++) p[e] /= sum;
        int i1 = 0;
#pragma unroll
        for (int e = 1; e < NEXP; e++) if (p[e] > p[i1]) i1 = e;
        int i2 = (i1 == 0) ? 1 : 0;
#pragma unroll
        for (int e = 0; e < NEXP; e++) if (e != i1 && p[e] > p[i2]) i2 = e;
        float s2 = p[i1] + p[i2];
        int pos = atomicAdd(&g_counts[i1], 1);
        g_tok[i1][pos] = warp;                 // slot 0
        pos = atomicAdd(&g_counts[i2], 1);
        g_tok[i2][pos] = warp | 0x10000;       // slot 1
        g_wslot[warp]         = p[i1] / s2;
        g_wslot[T_TOK + warp] = p[i2] / s2;
    }
}

// ---------------- GEMM1: inner = silu(Xg@W1^T)*(Xg@W3^T) --------------------
// block 128M x 64N(dual) x 32K, 8 warps 4Mx2N, warp 32x32 per matrix.
// 3-stage cp.async ring: [A 128xSS][B1 64xSS][B3 64xSS] floats per stage.
#define G1_SZ   36864u           // (128+64+64)*SS*4
#define G1_B1O  18432u           // 128*SS*4
#define G1_B3O  27648u           // 192*SS*4

__global__ void __launch_bounds__(256, 2)
gemm1_tc(const float* __restrict__ dummy) {
    extern __shared__ __align__(16) char smc[];
    const uint32_t sbase = (uint32_t)__cvta_generic_to_shared(smc);

    const int e = blockIdx.z;
    const int n = g_counts[e];
    const int row0 = blockIdx.y * 128;
    if (row0 >= n) return;
    const int ff0 = blockIdx.x * 64;

    const int tid = threadIdx.x;
    const int wid = tid >> 5, lane = tid & 31;
    const int wm = wid & 3, wn = wid >> 2;
    const int g = lane >> 2, t = lane & 3;

    // staging maps (iteration-invariant)
    const float* apt[4]; uint32_t aoffB[4];
#pragma unroll
    for (int i = 0; i < 4; i++) {
        int idx = tid + 256 * i;
        int arow = idx >> 3, aq = idx & 7;
        aoffB[i] = (uint32_t)(arow * SS + aq * 4) * 4u;
        int r = row0 + arow;
        int tok = (r < n) ? (g_tok[e][r] & 0xFFFF) : 0;
        apt[i] = g_xr + (size_t)tok * H_DIM + aq * 4;
    }
    const float* b1pt[2]; const float* b3pt[2]; uint32_t boffB[2];
#pragma unroll
    for (int i = 0; i < 2; i++) {
        int idx = tid + 256 * i;
        int brow = idx >> 3, bq = idx & 7;
        boffB[i] = (uint32_t)(brow * SS + bq * 4) * 4u;
        b1pt[i] = g_w1r + ((size_t)e * FF_DIM + ff0 + brow) * H_DIM + bq * 4;
        b3pt[i] = g_w3r + ((size_t)e * FF_DIM + ff0 + brow) * H_DIM + bq * 4;
    }

    auto issue = [&](int s) {
        uint32_t base = sbase + (uint32_t)(s % STAGES) * G1_SZ;
        int k0 = s * 32;
#pragma unroll
        for (int i = 0; i < 4; i++) CP16(base + aoffB[i], apt[i] + k0);
#pragma unroll
        for (int i = 0; i < 2; i++) {
            CP16(base + G1_B1O + boffB[i], b1pt[i] + k0);
            CP16(base + G1_B3O + boffB[i], b3pt[i] + k0);
        }
        CPCOMMIT();
    };

    float acc1[2][4][4], acc3[2][4][4];
#pragma unroll
    for (int mb = 0; mb < 2; mb++)
#pragma unroll
        for (int nb = 0; nb < 4; nb++)
#pragma unroll
            for (int j = 0; j < 4; j++) { acc1[mb][nb][j] = 0.f; acc3[mb][nb][j] = 0.f; }

    const int aL  = (wm * 32 + g) * SS + t;
    const int bL  = (wn * 32 + g) * SS + t;

    issue(0); issue(1);

    const int NIT = H_DIM / 32;
    for (int it = 0; it < NIT; ++it) {
        // invariant: need groups 0..it complete before reading slot it%3.
        // steady state: issued = it+2, wait_group(1) -> completed >= it+1. OK.
        // tail (it == NIT-1): issued = NIT, wait_group(1) only gives NIT-1 ->
        // must drain fully.
        if (it + 1 < NIT) CPWAIT1(); else CPWAIT0();
        __syncthreads();
        if (it + STAGES - 1 < NIT) issue(it + STAGES - 1);

        const int slot = it % STAGES;
        const uint32_t* Ab  = (const uint32_t*)(smc + slot * G1_SZ) + aL;
        const uint32_t* B1b = (const uint32_t*)(smc + slot * G1_SZ + G1_B1O) + bL;
        const uint32_t* B3b = (const uint32_t*)(smc + slot * G1_SZ + G1_B3O) + bL;

#pragma unroll
        for (int kk = 0; kk < 4; kk++) {
            uint32_t a[2][4], b1[4][2], b3[4][2];
#pragma unroll
            for (int mb = 0; mb < 2; mb++) {
                int base = mb * 16 * SS + kk * 8;
                a[mb][0] = Ab[base];
                a[mb][1] = Ab[base + 8 * SS];
                a[mb][2] = Ab[base + 4];
                a[mb][3] = Ab[base + 8 * SS + 4];
            }
#pragma unroll
            for (int nb = 0; nb < 4; nb++) {
                int bb = nb * 8 * SS + kk * 8;
                b1[nb][0] = B1b[bb]; b1[nb][1] = B1b[bb + 4];
                b3[nb][0] = B3b[bb]; b3[nb][1] = B3b[bb + 4];
            }
#pragma unroll
            for (int mb = 0; mb < 2; mb++)
#pragma unroll
                for (int nb = 0; nb < 4; nb++) {
                    mma8(acc1[mb][nb], a[mb], b1[nb]);
                    mma8(acc3[mb][nb], a[mb], b3[nb]);
                }
        }
        __syncthreads();
    }

    // fused SwiGLU epilogue -> g_inner (tf32-rounded for GEMM2's A operand)
#pragma unroll
    for (int mb = 0; mb < 2; mb++) {
        int r0 = row0 + wm * 32 + mb * 16 + g;
        int r1 = r0 + 8;
#pragma unroll
        for (int nb = 0; nb < 4; nb++) {
            int col = ff0 + wn * 32 + nb * 8 + 2 * t;
            if (r0 < n) {
                float a0 = acc1[mb][nb][0], a1 = acc1[mb][nb][1];
                uint2 v;
                v.x = tf32u((a0 / (1.f + expf(-a0))) * acc3[mb][nb][0]);
                v.y = tf32u((a1 / (1.f + expf(-a1))) * acc3[mb][nb][1]);
                *(uint2*)&g_inner[((size_t)e * T_TOK + r0) * FF_DIM + col] = v;
            }
            if (r1 < n) {
                float a2 = acc1[mb][nb][2], a3 = acc1[mb][nb][3];
                uint2 v;
                v.x = tf32u((a2 / (1.f + expf(-a2))) * acc3[mb][nb][2]);
                v.y = tf32u((a3 / (1.f + expf(-a3))) * acc3[mb][nb][3]);
                *(uint2*)&g_inner[((size_t)e * T_TOK + r1) * FF_DIM + col] = v;
            }
        }
    }
}

// ---------------- GEMM2: comb[slot][tok] = inner @ W2^T ---------------------
// block 128 x 128 x 32; 8 warps 4Mx2N, warp 32x64. 3-stage cp.async ring.
#define G2_SZ  36864u            // 2*128*SS*4
#define G2_BO  18432u

__global__ void __launch_bounds__(256, 2)
gemm2_tc(const float* __restrict__ dummy) {
    extern __shared__ __align__(16) char smc[];
    const uint32_t sbase = (uint32_t)__cvta_generic_to_shared(smc);

    const int e = blockIdx.z;
    const int n = g_counts[e];
    const int row0 = blockIdx.y * 128;
    if (row0 >= n) return;
    const int h0 = blockIdx.x * 128;

    const int tid = threadIdx.x;
    const int wid = tid >> 5, lane = tid & 31;
    const int wm = wid & 3, wn = wid >> 2;
    const int g = lane >> 2, t = lane & 3;

    const float* apt[4]; const float* bpt[4]; uint32_t offB[4];
#pragma unroll
    for (int i = 0; i < 4; i++) {
        int idx = tid + 256 * i;
        int row = idx >> 3, q = idx & 7;
        offB[i] = (uint32_t)(row * SS + q * 4) * 4u;
        apt[i] = g_inner + ((size_t)e * T_TOK + row0 + row) * FF_DIM + q * 4;
        bpt[i] = g_w2r + ((size_t)e * H_DIM + h0 + row) * FF_DIM + q * 4;
    }

    auto issue = [&](int s) {
        uint32_t base = sbase + (uint32_t)(s % STAGES) * G2_SZ;
        int k0 = s * 32;
#pragma unroll
        for (int i = 0; i < 4; i++) {
            CP16(base + offB[i], apt[i] + k0);
            CP16(base + G2_BO + offB[i], bpt[i] + k0);
        }
        CPCOMMIT();
    };

    float acc[2][8][4];
#pragma unroll
    for (int mb = 0; mb < 2; mb++)
#pragma unroll
        for (int nb = 0; nb < 8; nb++)
#pragma unroll
            for (int j = 0; j < 4; j++) acc[mb][nb][j] = 0.f;

    const int aL = (wm * 32 + g) * SS + t;
    const int bL = (wn * 64 + g) * SS + t;

    issue(0); issue(1);

    const int NIT = FF_DIM / 32;
    for (int it = 0; it < NIT; ++it) {
        if (it + 1 < NIT) CPWAIT1(); else CPWAIT0();
        __syncthreads();
        if (it + STAGES - 1 < NIT) issue(it + STAGES - 1);

        const int slot = it % STAGES;
        const uint32_t* Ab = (const uint32_t*)(smc + slot * G2_SZ) + aL;
        const uint32_t* Bb = (const uint32_t*)(smc + slot * G2_SZ + G2_BO) + bL;

#pragma unroll
        for (int kk = 0; kk < 4; kk++) {
            uint32_t a[2][4], b[8][2];
#pragma unroll
            for (int mb = 0; mb < 2; mb++) {
                int base = mb * 16 * SS + kk * 8;
                a[mb][0] = Ab[base];
                a[mb][1] = Ab[base + 8 * SS];
                a[mb][2] = Ab[base + 4];
                a[mb][3] = Ab[base + 8 * SS + 4];
            }
#pragma unroll
            for (int nb = 0; nb < 8; nb++) {
                int bb = nb * 8 * SS + kk * 8;
                b[nb][0] = Bb[bb]; b[nb][1] = Bb[bb + 4];
            }
#pragma unroll
            for (int mb = 0; mb < 2; mb++)
#pragma unroll
                for (int nb = 0; nb < 8; nb++)
                    mma8(acc[mb][nb], a[mb], b[nb]);
        }
        __syncthreads();
    }

    // non-atomic scatter into per-slot combine buffers
#pragma unroll
    for (int mb = 0; mb < 2; mb++) {
        int r0 = row0 + wm * 32 + mb * 16 + g;
        int r1 = r0 + 8;
        int pk0 = (r0 < n) ? g_tok[e][r0] : -1;
        int pk1 = (r1 < n) ? g_tok[e][r1] : -1;
        float* d0 = (pk0 >= 0)
            ? &g_comb[((size_t)(pk0 >> 16) * T_TOK + (pk0 & 0xFFFF)) * H_DIM] : 0;
        float* d1 = (pk1 >= 0)
            ? &g_comb[((size_t)(pk1 >> 16) * T_TOK + (pk1 & 0xFFFF)) * H_DIM] : 0;
#pragma unroll
        for (int nb = 0; nb < 8; nb++) {
            int col = h0 + wn * 64 + nb * 8 + 2 * t;
            if (d0) { float2 v; v.x = acc[mb][nb][0]; v.y = acc[mb][nb][1];
                      *(float2*)&d0[col] = v; }
            if (d1) { float2 v; v.x = acc[mb][nb][2]; v.y = acc[mb][nb][3];
                      *(float2*)&d1[col] = v; }
        }
    }
}

// ---------------- combine: out = w0*comb0 + w1*comb1 ------------------------
__global__ void combine_kernel(float* __restrict__ out) {
    int idx = blockIdx.x * blockDim.x + threadIdx.x;
    const int nq = T_TOK * H_DIM / 4;
    if (idx >= nq) return;
    int tk = idx / (H_DIM / 4);
    float w0 = g_wslot[tk], w1 = g_wslot[T_TOK + tk];
    float4 v0 = ((const float4*)g_comb)[idx];
    float4 v1 = ((const float4*)g_comb)[(size_t)(T_TOK * H_DIM / 4) + idx];
    float4 r;
    r.x = w0 * v0.x + w1 * v1.x;
    r.y = w0 * v0.y + w1 * v1.y;
    r.z = w0 * v0.z + w1 * v1.z;
    r.w = w0 * v0.w + w1 * v1.w;
    ((float4*)out)[idx] = r;
}

// ---------------- launch -----------------------------------------------------
extern "C" void kernel_launch(void* const* d_in, const int* in_sizes, int n_in,
                              void* d_out, int out_size) {
    const float* x  = (const float*)d_in[0];  // [2,2048,1024]
    const float* gw = (const float*)d_in[1];  // [8,1024]
    const float* w1 = (const float*)d_in[2];  // [8,2048,1024]
    const float* w2 = (const float*)d_in[3];  // [8,1024,2048]
    const float* w3 = (const float*)d_in[4];  // [8,2048,1024]
    float* out = (float*)d_out;

    const size_t final_elems = (size_t)T_TOK * H_DIM;
    int write_logits = ((size_t)out_size >= final_elems + (size_t)T_TOK * NEXP) ? 1 : 0;
    float* logits = out + final_elems;

    const int dynsm = STAGES * 36864;   // 110592
    cudaFuncSetAttribute(gemm1_tc, cudaFuncAttributeMaxDynamicSharedMemorySize, dynsm);
    cudaFuncSetAttribute(gemm2_tc, cudaFuncAttributeMaxDynamicSharedMemorySize, dynsm);

    const size_t wq = (size_t)NEXP * FF_DIM * H_DIM / 4;
    round_weights_kernel<<<(int)((wq + 255) / 256), 256>>>(w1, w2, w3);
    router_kernel<<<T_TOK / 8, 256>>>(x, gw, logits, write_logits);

    dim3 g1(FF_DIM / 64, T_TOK / 128, NEXP);   // (32, 32, 8)
    gemm1_tc<<<g1, 256, dynsm>>>(x);

    dim3 g2(H_DIM / 128, T_TOK / 128, NEXP);   // (8, 32, 8)
    gemm2_tc<<<g2, 256, dynsm>>>(x);

    combine_kernel<<<(T_TOK * H_DIM / 4 + 255) / 256, 256>>>(out);
}

// round 6
// speedup vs baseline: 3.2901x; 1.0870x over previous
#include <cuda_runtime.h>
#include <math.h>
#include <stdint.h>

#define T_TOK 4096
#define H_DIM 1024
#define FF_DIM 2048
#define NEXP 8
#define SS 36
#define STAGES 3

// ---------------- device scratch (allocation-guard safe) --------------------
__device__ int   g_counts[NEXP];
__device__ int   g_tok[NEXP][T_TOK];            // packed: tok | slot<<16
__device__ float g_wslot[2 * T_TOK];
__device__ float g_inner[(size_t)NEXP * T_TOK * FF_DIM];   // 256 MB
__device__ float g_comb[(size_t)2 * T_TOK * H_DIM];        // 32 MB
__device__ float g_w1r[(size_t)NEXP * FF_DIM * H_DIM];     // 64 MB (tf32-rounded)
__device__ float g_w3r[(size_t)NEXP * FF_DIM * H_DIM];     // 64 MB
__device__ float g_w2r[(size_t)NEXP * H_DIM * FF_DIM];     // 64 MB
__device__ float g_xr[(size_t)T_TOK * H_DIM];              // 16 MB

// ---------------- helpers ----------------------------------------------------
__device__ __forceinline__ uint32_t tf32u(float x) {
    uint32_t u; asm("cvt.rna.tf32.f32 %0, %1;" : "=r"(u) : "f"(x)); return u;
}
__device__ __forceinline__ uint4 cvt4(float4 v) {
    uint4 u; u.x = tf32u(v.x); u.y = tf32u(v.y); u.z = tf32u(v.z); u.w = tf32u(v.w);
    return u;
}
__device__ __forceinline__ void mma8(float* c, const uint32_t* a, const uint32_t* b) {
    asm volatile(
        "mma.sync.aligned.m16n8k8.row.col.f32.tf32.tf32.f32 "
        "{%0,%1,%2,%3}, {%4,%5,%6,%7}, {%8,%9}, {%0,%1,%2,%3};"
        : "+f"(c[0]), "+f"(c[1]), "+f"(c[2]), "+f"(c[3])
        : "r"(a[0]), "r"(a[1]), "r"(a[2]), "r"(a[3]), "r"(b[0]), "r"(b[1]));
}
#define LDSM4(r0, r1, r2, r3, addr) \
    asm volatile("ldmatrix.sync.aligned.m8n8.x4.shared.b16 {%0,%1,%2,%3}, [%4];" \
                 : "=r"(r0), "=r"(r1), "=r"(r2), "=r"(r3) : "r"(addr))
#define CP16(dst, src) \
    asm volatile("cp.async.cg.shared.global [%0], [%1], 16;" \
                 :: "r"(dst), "l"(src) : "memory")
#define CPCOMMIT() asm volatile("cp.async.commit_group;" ::: "memory")
#define CPWAIT1()  asm volatile("cp.async.wait_group 1;" ::: "memory")
#define CPWAIT0()  asm volatile("cp.async.wait_group 0;" ::: "memory")

// ---------------- prolog: round weights to tf32, zero counts ----------------
__global__ void round_weights_kernel(const float* __restrict__ w1,
                                     const float* __restrict__ w2,
                                     const float* __restrict__ w3) {
    size_t i = (size_t)blockIdx.x * blockDim.x + threadIdx.x;
    const size_t n4 = (size_t)NEXP * FF_DIM * H_DIM / 4;
    if (i < n4) {
        ((uint4*)g_w1r)[i] = cvt4(((const float4*)w1)[i]);
        ((uint4*)g_w3r)[i] = cvt4(((const float4*)w3)[i]);
        ((uint4*)g_w2r)[i] = cvt4(((const float4*)w2)[i]);
    }
    if (blockIdx.x == 0 && threadIdx.x < NEXP) g_counts[threadIdx.x] = 0;
}

// ---------------- router: 1 warp per token; also writes rounded x -----------
__global__ void router_kernel(const float* __restrict__ x,
                              const float* __restrict__ gw,
                              float* __restrict__ logits_out,
                              int write_logits) {
    int warp = (blockIdx.x * blockDim.x + threadIdx.x) >> 5;
    int lane = threadIdx.x & 31;
    if (warp >= T_TOK) return;

    const float* xr = x + (size_t)warp * H_DIM;
    float xv[32];
#pragma unroll
    for (int i = 0; i < 32; i++) xv[i] = xr[lane + 32 * i];
#pragma unroll
    for (int i = 0; i < 32; i++)
        ((uint32_t*)g_xr)[(size_t)warp * H_DIM + lane + 32 * i] = tf32u(xv[i]);

    float lg[NEXP];
#pragma unroll
    for (int e = 0; e < NEXP; e++) {
        const float* g = gw + (size_t)e * H_DIM;
        float s = 0.f;
#pragma unroll
        for (int i = 0; i < 32; i++) s += xv[i] * g[lane + 32 * i];
#pragma unroll
        for (int o = 16; o > 0; o >>= 1) s += __shfl_xor_sync(0xffffffffu, s, o);
        lg[e] = s;
    }

    if (lane == 0) {
        if (write_logits) {
#pragma unroll
            for (int e = 0; e < NEXP; e++)
                logits_out[(size_t)warp * NEXP + e] = lg[e];
        }
        float mx = lg[0];
#pragma unroll
        for (int e = 1; e < NEXP; e++) mx = fmaxf(mx, lg[e]);
        float p[NEXP], sum = 0.f;
#pragma unroll
        for (int e = 0; e < NEXP; e++) { p[e] = expf(lg[e] - mx); sum += p[e]; }
#pragma unroll
        for (int e = 0; e < NEXP; e++) p[e] /= sum;
        int i1 = 0;
#pragma unroll
        for (int e = 1; e < NEXP; e++) if (p[e] > p[i1]) i1 = e;
        int i2 = (i1 == 0) ? 1 : 0;
#pragma unroll
        for (int e = 0; e < NEXP; e++) if (e != i1 && p[e] > p[i2]) i2 = e;
        float s2 = p[i1] + p[i2];
        int pos = atomicAdd(&g_counts[i1], 1);
        g_tok[i1][pos] = warp;                 // slot 0
        pos = atomicAdd(&g_counts[i2], 1);
        g_tok[i2][pos] = warp | 0x10000;       // slot 1
        g_wslot[warp]         = p[i1] / s2;
        g_wslot[T_TOK + warp] = p[i2] / s2;
    }
}

// ---------------- GEMM1: inner = silu(Xg@W1^T)*(Xg@W3^T) --------------------
// block 128M x 64N(dual) x 32K, 8 warps 4Mx2N, warp 32x32 per matrix.
// 3-stage cp.async ring: [A 128xSS][B1 64xSS][B3 64xSS] floats per stage.
#define G1_SZ   36864u           // (128+64+64)*SS*4
#define G1_B1O  18432u           // 128*SS*4
#define G1_B3O  27648u           // 192*SS*4

__global__ void __launch_bounds__(256, 2)
gemm1_tc(const float* __restrict__ dummy) {
    extern __shared__ __align__(16) char smc[];
    const uint32_t sbase = (uint32_t)__cvta_generic_to_shared(smc);

    const int e = blockIdx.z;
    const int n = g_counts[e];
    const int row0 = blockIdx.y * 128;
    if (row0 >= n) return;
    const int ff0 = blockIdx.x * 64;

    const int tid = threadIdx.x;
    const int wid = tid >> 5, lane = tid & 31;
    const int wm = wid & 3, wn = wid >> 2;
    const int g = lane >> 2, t = lane & 3;

    // staging maps (iteration-invariant)
    const float* apt[4]; uint32_t aoffB[4];
#pragma unroll
    for (int i = 0; i < 4; i++) {
        int idx = tid + 256 * i;
        int arow = idx >> 3, aq = idx & 7;
        aoffB[i] = (uint32_t)(arow * SS + aq * 4) * 4u;
        int r = row0 + arow;
        int tok = (r < n) ? (g_tok[e][r] & 0xFFFF) : 0;
        apt[i] = g_xr + (size_t)tok * H_DIM + aq * 4;
    }
    const float* b1pt[2]; const float* b3pt[2]; uint32_t boffB[2];
#pragma unroll
    for (int i = 0; i < 2; i++) {
        int idx = tid + 256 * i;
        int brow = idx >> 3, bq = idx & 7;
        boffB[i] = (uint32_t)(brow * SS + bq * 4) * 4u;
        b1pt[i] = g_w1r + ((size_t)e * FF_DIM + ff0 + brow) * H_DIM + bq * 4;
        b3pt[i] = g_w3r + ((size_t)e * FF_DIM + ff0 + brow) * H_DIM + bq * 4;
    }

    auto issue = [&](int s) {
        uint32_t base = sbase + (uint32_t)(s % STAGES) * G1_SZ;
        int k0 = s * 32;
#pragma unroll
        for (int i = 0; i < 4; i++) CP16(base + aoffB[i], apt[i] + k0);
#pragma unroll
        for (int i = 0; i < 2; i++) {
            CP16(base + G1_B1O + boffB[i], b1pt[i] + k0);
            CP16(base + G1_B3O + boffB[i], b3pt[i] + k0);
        }
        CPCOMMIT();
    };

    float acc1[2][4][4], acc3[2][4][4];
#pragma unroll
    for (int mb = 0; mb < 2; mb++)
#pragma unroll
        for (int nb = 0; nb < 4; nb++)
#pragma unroll
            for (int j = 0; j < 4; j++) { acc1[mb][nb][j] = 0.f; acc3[mb][nb][j] = 0.f; }

    // ldmatrix per-lane byte offsets (kk=0); +32B per kk step
    const int lr = lane & 7, lq1 = (lane >> 3) & 1, lq2 = (lane >> 4) & 1;
    uint32_t aLb[2];
#pragma unroll
    for (int mb = 0; mb < 2; mb++)
        aLb[mb] = (uint32_t)((wm * 32 + mb * 16 + lr + lq1 * 8) * SS + lq2 * 4) * 4u;
    uint32_t bLb[2];   // nb pairs p=0,1 (covering nb=2p, 2p+1)
#pragma unroll
    for (int p = 0; p < 2; p++)
        bLb[p] = (uint32_t)((wn * 32 + (2 * p + lq2) * 8 + lr) * SS + lq1 * 4) * 4u;

    issue(0); issue(1);

    const int NIT = H_DIM / 32;
    for (int it = 0; it < NIT; ++it) {
        if (it + 1 < NIT) CPWAIT1(); else CPWAIT0();
        __syncthreads();
        if (it + STAGES - 1 < NIT) issue(it + STAGES - 1);

        const uint32_t sb  = sbase + (uint32_t)(it % STAGES) * G1_SZ;
        const uint32_t b1b = sb + G1_B1O;
        const uint32_t b3b = sb + G1_B3O;

#pragma unroll
        for (int kk = 0; kk < 4; kk++) {
            const uint32_t ko = (uint32_t)kk * 32u;
            uint32_t a[2][4], b1[4][2], b3[4][2];
#pragma unroll
            for (int mb = 0; mb < 2; mb++)
                LDSM4(a[mb][0], a[mb][1], a[mb][2], a[mb][3], sb + aLb[mb] + ko);
#pragma unroll
            for (int p = 0; p < 2; p++) {
                LDSM4(b1[2*p][0], b1[2*p][1], b1[2*p+1][0], b1[2*p+1][1], b1b + bLb[p] + ko);
                LDSM4(b3[2*p][0], b3[2*p][1], b3[2*p+1][0], b3[2*p+1][1], b3b + bLb[p] + ko);
            }
#pragma unroll
            for (int mb = 0; mb < 2; mb++)
#pragma unroll
                for (int nb = 0; nb < 4; nb++) {
                    mma8(acc1[mb][nb], a[mb], b1[nb]);
                    mma8(acc3[mb][nb], a[mb], b3[nb]);
                }
        }
        // no trailing barrier: next iteration's (wait + barrier) protects the
        // slot that issue() overwrites (it was last read one iteration ago).
    }

    // fused SwiGLU epilogue -> g_inner (tf32-rounded for GEMM2's A operand)
#pragma unroll
    for (int mb = 0; mb < 2; mb++) {
        int r0 = row0 + wm * 32 + mb * 16 + g;
        int r1 = r0 + 8;
#pragma unroll
        for (int nb = 0; nb < 4; nb++) {
            int col = ff0 + wn * 32 + nb * 8 + 2 * t;
            if (r0 < n) {
                float a0 = acc1[mb][nb][0], a1 = acc1[mb][nb][1];
                uint2 v;
                v.x = tf32u((a0 / (1.f + expf(-a0))) * acc3[mb][nb][0]);
                v.y = tf32u((a1 / (1.f + expf(-a1))) * acc3[mb][nb][1]);
                *(uint2*)&g_inner[((size_t)e * T_TOK + r0) * FF_DIM + col] = v;
            }
            if (r1 < n) {
                float a2 = acc1[mb][nb][2], a3 = acc1[mb][nb][3];
                uint2 v;
                v.x = tf32u((a2 / (1.f + expf(-a2))) * acc3[mb][nb][2]);
                v.y = tf32u((a3 / (1.f + expf(-a3))) * acc3[mb][nb][3]);
                *(uint2*)&g_inner[((size_t)e * T_TOK + r1) * FF_DIM + col] = v;
            }
        }
    }
}

// ---------------- GEMM2: comb[slot][tok] = inner @ W2^T ---------------------
// block 128 x 128 x 32; 8 warps 4Mx2N, warp 32x64. 3-stage cp.async ring.
#define G2_SZ  36864u            // 2*128*SS*4
#define G2_BO  18432u

__global__ void __launch_bounds__(256, 2)
gemm2_tc(const float* __restrict__ dummy) {
    extern __shared__ __align__(16) char smc[];
    const uint32_t sbase = (uint32_t)__cvta_generic_to_shared(smc);

    const int e = blockIdx.z;
    const int n = g_counts[e];
    const int row0 = blockIdx.y * 128;
    if (row0 >= n) return;
    const int h0 = blockIdx.x * 128;

    const int tid = threadIdx.x;
    const int wid = tid >> 5, lane = tid & 31;
    const int wm = wid & 3, wn = wid >> 2;
    const int g = lane >> 2, t = lane & 3;

    const float* apt[4]; const float* bpt[4]; uint32_t offB[4];
#pragma unroll
    for (int i = 0; i < 4; i++) {
        int idx = tid + 256 * i;
        int row = idx >> 3, q = idx & 7;
        offB[i] = (uint32_t)(row * SS + q * 4) * 4u;
        apt[i] = g_inner + ((size_t)e * T_TOK + row0 + row) * FF_DIM + q * 4;
        bpt[i] = g_w2r + ((size_t)e * H_DIM + h0 + row) * FF_DIM + q * 4;
    }

    auto issue = [&](int s) {
        uint32_t base = sbase + (uint32_t)(s % STAGES) * G2_SZ;
        int k0 = s * 32;
#pragma unroll
        for (int i = 0; i < 4; i++) {
            CP16(base + offB[i], apt[i] + k0);
            CP16(base + G2_BO + offB[i], bpt[i] + k0);
        }
        CPCOMMIT();
    };

    float acc[2][8][4];
#pragma unroll
    for (int mb = 0; mb < 2; mb++)
#pragma unroll
        for (int nb = 0; nb < 8; nb++)
#pragma unroll
            for (int j = 0; j < 4; j++) acc[mb][nb][j] = 0.f;

    const int lr = lane & 7, lq1 = (lane >> 3) & 1, lq2 = (lane >> 4) & 1;
    uint32_t aLb[2];
#pragma unroll
    for (int mb = 0; mb < 2; mb++)
        aLb[mb] = (uint32_t)((wm * 32 + mb * 16 + lr + lq1 * 8) * SS + lq2 * 4) * 4u;
    uint32_t bLb[4];   // nb pairs p=0..3 (covering nb=2p, 2p+1)
#pragma unroll
    for (int p = 0; p < 4; p++)
        bLb[p] = (uint32_t)((wn * 64 + (2 * p + lq2) * 8 + lr) * SS + lq1 * 4) * 4u;

    issue(0); issue(1);

    const int NIT = FF_DIM / 32;
    for (int it = 0; it < NIT; ++it) {
        if (it + 1 < NIT) CPWAIT1(); else CPWAIT0();
        __syncthreads();
        if (it + STAGES - 1 < NIT) issue(it + STAGES - 1);

        const uint32_t sb = sbase + (uint32_t)(it % STAGES) * G2_SZ;
        const uint32_t bb = sb + G2_BO;

#pragma unroll
        for (int kk = 0; kk < 4; kk++) {
            const uint32_t ko = (uint32_t)kk * 32u;
            uint32_t a[2][4], b[8][2];
#pragma unroll
            for (int mb = 0; mb < 2; mb++)
                LDSM4(a[mb][0], a[mb][1], a[mb][2], a[mb][3], sb + aLb[mb] + ko);
#pragma unroll
            for (int p = 0; p < 4; p++)
                LDSM4(b[2*p][0], b[2*p][1], b[2*p+1][0], b[2*p+1][1], bb + bLb[p] + ko);
#pragma unroll
            for (int mb = 0; mb < 2; mb++)
#pragma unroll
                for (int nb = 0; nb < 8; nb++)
                    mma8(acc[mb][nb], a[mb], b[nb]);
        }
    }

    // non-atomic scatter into per-slot combine buffers
#pragma unroll
    for (int mb = 0; mb < 2; mb++) {
        int r0 = row0 + wm * 32 + mb * 16 + g;
        int r1 = r0 + 8;
        int pk0 = (r0 < n) ? g_tok[e][r0] : -1;
        int pk1 = (r1 < n) ? g_tok[e][r1] : -1;
        float* d0 = (pk0 >= 0)
            ? &g_comb[((size_t)(pk0 >> 16) * T_TOK + (pk0 & 0xFFFF)) * H_DIM] : 0;
        float* d1 = (pk1 >= 0)
            ? &g_comb[((size_t)(pk1 >> 16) * T_TOK + (pk1 & 0xFFFF)) * H_DIM] : 0;
#pragma unroll
        for (int nb = 0; nb < 8; nb++) {
            int col = h0 + wn * 64 + nb * 8 + 2 * t;
            if (d0) { float2 v; v.x = acc[mb][nb][0]; v.y = acc[mb][nb][1];
                      *(float2*)&d0[col] = v; }
            if (d1) { float2 v; v.x = acc[mb][nb][2]; v.y = acc[mb][nb][3];
                      *(float2*)&d1[col] = v; }
        }
    }
}

// ---------------- combine: out = w0*comb0 + w1*comb1 ------------------------
__global__ void combine_kernel(float* __restrict__ out) {
    int idx = blockIdx.x * blockDim.x + threadIdx.x;
    const int nq = T_TOK * H_DIM / 4;
    if (idx >= nq) return;
    int tk = idx / (H_DIM / 4);
    float w0 = g_wslot[tk], w1 = g_wslot[T_TOK + tk];
    float4 v0 = ((const float4*)g_comb)[idx];
    float4 v1 = ((const float4*)g_comb)[(size_t)(T_TOK * H_DIM / 4) + idx];
    float4 r;
    r.x = w0 * v0.x + w1 * v1.x;
    r.y = w0 * v0.y + w1 * v1.y;
    r.z = w0 * v0.z + w1 * v1.z;
    r.w = w0 * v0.w + w1 * v1.w;
    ((float4*)out)[idx] = r;
}

// ---------------- launch -----------------------------------------------------
extern "C" void kernel_launch(void* const* d_in, const int* in_sizes, int n_in,
                              void* d_out, int out_size) {
    const float* x  = (const float*)d_in[0];  // [2,2048,1024]
    const float* gw = (const float*)d_in[1];  // [8,1024]
    const float* w1 = (const float*)d_in[2];  // [8,2048,1024]
    const float* w2 = (const float*)d_in[3];  // [8,1024,2048]
    const float* w3 = (const float*)d_in[4];  // [8,2048,1024]
    float* out = (float*)d_out;

    const size_t final_elems = (size_t)T_TOK * H_DIM;
    int write_logits = ((size_t)out_size >= final_elems + (size_t)T_TOK * NEXP) ? 1 : 0;
    float* logits = out + final_elems;

    const int dynsm = STAGES * 36864;   // 110592
    cudaFuncSetAttribute(gemm1_tc, cudaFuncAttributeMaxDynamicSharedMemorySize, dynsm);
    cudaFuncSetAttribute(gemm2_tc, cudaFuncAttributeMaxDynamicSharedMemorySize, dynsm);

    const size_t wq = (size_t)NEXP * FF_DIM * H_DIM / 4;
    round_weights_kernel<<<(int)((wq + 255) / 256), 256>>>(w1, w2, w3);
    router_kernel<<<T_TOK / 8, 256>>>(x, gw, logits, write_logits);

    dim3 g1(FF_DIM / 64, T_TOK / 128, NEXP);   // (32, 32, 8)
    gemm1_tc<<<g1, 256, dynsm>>>(x);

    dim3 g2(H_DIM / 128, T_TOK / 128, NEXP);   // (8, 32, 8)
    gemm2_tc<<<g2, 256, dynsm>>>(x);

    combine_kernel<<<(T_TOK * H_DIM / 4 + 255) / 256, 256>>>(out);
}